// round 2
// baseline (speedup 1.0000x reference)
#include <cuda_runtime.h>
#include <cuda_bf16.h>

#define DIMC 64
#define HID  170
#define HW   256

// h scratch: [4][170][256][256] f32 = 178 MB (static __device__ => allocation-free)
__device__ float g_h[(size_t)4 * HID * HW * HW];

// ---------------------------------------------------------------------------
// Pass 1: 1x1 conv (64 -> 170) + 2x2 patch spectral filter (4x4 Hadamard map)
// grid (2, 128, 4): (col-half, patch-row, batch). block 256.
// Tile: pixel rows {2*py, 2*py+1}, cols [128*bx, 128*bx+128) => 64 patches.
// ---------------------------------------------------------------------------
extern "C" __global__ void __launch_bounds__(256, 2)
pass1_kernel(const float* __restrict__ x, const float* __restrict__ W_in,
             const float* __restrict__ fftf)
{
    extern __shared__ float smem[];
    float* sx = smem;               // [64][256] patch-grouped: sx[k*256 + 4*P + s], s = 2*r + cc
    float* sW = sx + 64 * 256;      // [170][64]
    float* sF = sW + HID * 64;      // [170][4]

    const int tid = threadIdx.x;
    const int b   = blockIdx.z;
    const int py  = blockIdx.y;          // patch row (pixel rows 2*py, 2*py+1)
    const int c0  = blockIdx.x * 128;    // pixel col base

    // Stage weights + filter
    for (int i = tid; i < HID * 64; i += 256) sW[i] = W_in[i];
    for (int i = tid; i < HID * 4;  i += 256) sF[i] = fftf[i];

    // Stage x tile: 64 ch x 2 rows x 128 cols as float4 (coalesced), patch-grouped in smem
    const float* xb = x + (size_t)b * 64 * HW * HW;
    for (int idx = tid; idx < 4096; idx += 256) {
        int k  = idx >> 6;          // channel 0..63
        int r  = (idx >> 5) & 1;    // row within patch
        int c4 = idx & 31;          // float4 column
        float4 v = *(const float4*)(xb + ((size_t)k * HW + 2 * py + r) * HW + c0 + 4 * c4);
        int base = k * 256 + 8 * c4 + 2 * r;
        *(float2*)(sx + base)     = make_float2(v.x, v.y);   // patch 2*c4,   slots 2r, 2r+1
        *(float2*)(sx + base + 4) = make_float2(v.z, v.w);   // patch 2*c4+1, slots 2r, 2r+1
    }
    __syncthreads();

    const int i = tid >> 4;   // channel slot 0..15
    const int j = tid & 15;   // patch slot: handles patches j, j+16, j+32, j+48

    for (int c = i; c < HID; c += 16) {
        float acc[4][4];
        #pragma unroll
        for (int p = 0; p < 4; p++)
            #pragma unroll
            for (int s = 0; s < 4; s++) acc[p][s] = 0.f;

        const float4* wr = (const float4*)(sW + c * 64);
        #pragma unroll
        for (int k4 = 0; k4 < 16; k4++) {
            float4 w4 = wr[k4];
            float wv[4] = {w4.x, w4.y, w4.z, w4.w};
            #pragma unroll
            for (int kk = 0; kk < 4; kk++) {
                const float* row = sx + (k4 * 4 + kk) * 256;
                float w = wv[kk];
                #pragma unroll
                for (int p = 0; p < 4; p++) {
                    float4 v = *(const float4*)(row + 4 * (j + 16 * p));
                    acc[p][0] += w * v.x;
                    acc[p][1] += w * v.y;
                    acc[p][2] += w * v.z;
                    acc[p][3] += w * v.w;
                }
            }
        }

        // Patch spectral filter: x' = (1/4) * H * diag(f) * H * x
        float f0 = sF[c * 4 + 0], f1 = sF[c * 4 + 1];
        float f2 = sF[c * 4 + 2], f3 = sF[c * 4 + 3];
        float* hb = g_h + (((size_t)b * HID + c) * HW + 2 * py) * HW + c0;
        #pragma unroll
        for (int p = 0; p < 4; p++) {
            float a  = acc[p][0], bb = acc[p][1];
            float cc = acc[p][2], dd = acc[p][3];
            float X0 = a + bb + cc + dd;
            float X1 = a - bb + cc - dd;
            float X2 = a + bb - cc - dd;
            float X3 = a - bb - cc + dd;
            X0 *= 0.25f * f0; X1 *= 0.25f * f1; X2 *= 0.25f * f2; X3 *= 0.25f * f3;
            float o0 = X0 + X1 + X2 + X3;
            float o1 = X0 - X1 + X2 - X3;
            float o2 = X0 + X1 - X2 - X3;
            float o3 = X0 - X1 - X2 + X3;
            int P = j + 16 * p;
            *(float2*)(hb + 2 * P)      = make_float2(o0, o1);
            *(float2*)(hb + HW + 2 * P) = make_float2(o2, o3);
        }
    }
}

// ---------------------------------------------------------------------------
// Pass 2: depthwise 3x3 (170 groups x 2 outs) + exact GELU gate + 1x1 conv (170->64)
// grid (8, 32, 4): tile 32 wide x 8 tall. block 256 (warp = one pixel row).
// gated[c] = gelu(dw(h[c/2], Wdw[c])) * dw(h[85+c/2], Wdw[170+c])
// out[o]   = sum_c W_out[o][c] * gated[c]
// ---------------------------------------------------------------------------
extern "C" __global__ void __launch_bounds__(256, 2)
pass2_kernel(const float* __restrict__ W_dw, const float* __restrict__ W_out,
             float* __restrict__ out)
{
    extern __shared__ float smem[];
    float* sWo = smem;               // [170][64]  W_out transposed: sWo[c*64 + o]
    float* sDw = sWo + HID * 64;     // [340][9]
    float* sh  = sDw + 340 * 9;      // [2][10][36]

    const int tid = threadIdx.x;
    const int tx = tid & 31, ty = tid >> 5;
    const int b  = blockIdx.z;
    const int x0 = blockIdx.x * 32, y0 = blockIdx.y * 8;

    for (int idx = tid; idx < HID * 64; idx += 256) {
        int c = idx >> 6, o = idx & 63;
        sWo[idx] = W_out[o * HID + c];
    }
    for (int idx = tid; idx < 340 * 9; idx += 256) sDw[idx] = W_dw[idx];

    float acc[64];
    #pragma unroll
    for (int o = 0; o < 64; o++) acc[o] = 0.f;

    for (int g = 0; g < 85; g++) {
        __syncthreads();
        // stage h[g] and h[85+g] tiles, 10 rows x 34 cols each, zero-padded at edges
        for (int idx = tid; idx < 680; idx += 256) {
            int ch  = idx / 340;
            int rem = idx - ch * 340;
            int row = rem / 34, col = rem - row * 34;
            int gy = y0 - 1 + row, gx = x0 - 1 + col;
            float v = 0.f;
            if (gy >= 0 && gy < HW && gx >= 0 && gx < HW) {
                int hc = ch ? (85 + g) : g;
                v = g_h[(((size_t)b * HID + hc) * HW + gy) * HW + gx];
            }
            sh[ch * 360 + row * 36 + col] = v;
        }
        __syncthreads();

        #pragma unroll
        for (int sub = 0; sub < 2; sub++) {
            int c = 2 * g + sub;
            const float* w1 = sDw + c * 9;
            const float* w2 = sDw + (170 + c) * 9;
            float x1 = 0.f, x2 = 0.f;
            #pragma unroll
            for (int ky = 0; ky < 3; ky++) {
                #pragma unroll
                for (int kx = 0; kx < 3; kx++) {
                    x1 += w1[ky * 3 + kx] * sh[(ty + ky) * 36 + tx + kx];
                    x2 += w2[ky * 3 + kx] * sh[360 + (ty + ky) * 36 + tx + kx];
                }
            }
            float gated = x1 * normcdff(x1) * x2;   // exact GELU(x1) * x2
            const float4* wo = (const float4*)(sWo + c * 64);
            #pragma unroll
            for (int o4 = 0; o4 < 16; o4++) {
                float4 w = wo[o4];
                acc[4 * o4 + 0] += w.x * gated;
                acc[4 * o4 + 1] += w.y * gated;
                acc[4 * o4 + 2] += w.z * gated;
                acc[4 * o4 + 3] += w.w * gated;
            }
        }
    }

    float* ob = out + (((size_t)b * 64) * HW + y0 + ty) * HW + x0 + tx;
    #pragma unroll
    for (int o = 0; o < 64; o++)
        ob[(size_t)o * HW * HW] = acc[o];
}

// ---------------------------------------------------------------------------
extern "C" void kernel_launch(void* const* d_in, const int* in_sizes, int n_in,
                              void* d_out, int out_size)
{
    const float* x     = (const float*)d_in[0];
    const float* W_in  = (const float*)d_in[1];
    const float* fftf  = (const float*)d_in[2];
    const float* W_dw  = (const float*)d_in[3];
    const float* W_out = (const float*)d_in[4];
    float* out = (float*)d_out;

    const int smem1 = (64 * 256 + HID * 64 + HID * 4) * (int)sizeof(float);   // ~109 KB
    const int smem2 = (HID * 64 + 340 * 9 + 2 * 360) * (int)sizeof(float);    // ~57 KB
    cudaFuncSetAttribute(pass1_kernel, cudaFuncAttributeMaxDynamicSharedMemorySize, smem1);
    cudaFuncSetAttribute(pass2_kernel, cudaFuncAttributeMaxDynamicSharedMemorySize, smem2);

    pass1_kernel<<<dim3(2, 128, 4), 256, smem1>>>(x, W_in, fftf);
    pass2_kernel<<<dim3(8, 32, 4), 256, smem2>>>(W_dw, W_out, out);
}

// round 3
// speedup vs baseline: 5.0528x; 5.0528x over previous
#include <cuda_runtime.h>
#include <cuda_bf16.h>

#define DIMC 64
#define HID  170
#define HW   256
#define HWHW (HW * HW)

// h scratch: [4][170][256][256] f32 = 178 MB (static __device__ => allocation-free)
__device__ float g_h[(size_t)4 * HID * HW * HW];

// Packed dual-FMA (Blackwell f32x2 pipe): d = a*b + c on 2 floats per instr.
__device__ __forceinline__ float2 ffma2(float2 a, float2 b, float2 c) {
    float2 d;
    asm("fma.rn.f32x2 %0, %1, %2, %3;"
        : "=l"(reinterpret_cast<unsigned long long&>(d))
        : "l"(reinterpret_cast<const unsigned long long&>(a)),
          "l"(reinterpret_cast<const unsigned long long&>(b)),
          "l"(reinterpret_cast<const unsigned long long&>(c)));
    return d;
}

// ---------------------------------------------------------------------------
// Pass 1: 1x1 conv (64 -> 170) + 2x2 patch spectral filter (4x4 Hadamard map)
// grid (2, 128, 4). block 256. Tile: 2 pixel rows x 128 cols => 64 patches.
// Each thread: 2 channels x 4 patches (x reuse 2x), W_in via L1 ldg broadcast.
// ---------------------------------------------------------------------------
extern "C" __global__ void __launch_bounds__(256)
pass1_kernel(const float* __restrict__ x, const float* __restrict__ W_in,
             const float* __restrict__ fftf)
{
    extern __shared__ float smem[];
    float* sx = smem;               // [64][256] patch-grouped: sx[k*256 + 4*P + s], s = 2*r + cc
    float* sF = sx + 64 * 256;      // [170][4]

    const int tid = threadIdx.x;
    const int b   = blockIdx.z;
    const int py  = blockIdx.y;          // patch row (pixel rows 2*py, 2*py+1)
    const int c0b = blockIdx.x * 128;    // pixel col base

    for (int i = tid; i < HID * 4; i += 256) sF[i] = fftf[i];

    // Stage x tile: 64 ch x 2 rows x 128 cols as float4 (coalesced), patch-grouped
    const float* xb = x + (size_t)b * 64 * HWHW;
    for (int idx = tid; idx < 4096; idx += 256) {
        int k  = idx >> 6;          // channel 0..63
        int r  = (idx >> 5) & 1;    // row within patch
        int c4 = idx & 31;          // float4 column
        float4 v = *(const float4*)(xb + ((size_t)k * HW + 2 * py + r) * HW + c0b + 4 * c4);
        int base = k * 256 + 8 * c4 + 2 * r;
        *(float2*)(sx + base)     = make_float2(v.x, v.y);
        *(float2*)(sx + base + 4) = make_float2(v.z, v.w);
    }
    __syncthreads();

    const int i = tid >> 4;   // channel slot 0..15
    const int j = tid & 15;   // patch slot: patches j, j+16, j+32, j+48

    for (int cb = 0; cb < 192; cb += 32) {
        const int c0 = cb + i;
        const int c1 = cb + 16 + i;
        if (c0 >= HID) continue;
        const bool v1 = (c1 < HID);

        float2 accA[4][2], accB[4][2];
        #pragma unroll
        for (int p = 0; p < 4; p++) {
            accA[p][0] = accA[p][1] = make_float2(0.f, 0.f);
            accB[p][0] = accB[p][1] = make_float2(0.f, 0.f);
        }

        const float4* wr0 = (const float4*)(W_in + c0 * 64);
        const float4* wr1 = (const float4*)(W_in + (v1 ? c1 : c0) * 64);

        #pragma unroll
        for (int k4 = 0; k4 < 16; k4++) {
            float4 wa = __ldg(wr0 + k4);
            float4 wb = __ldg(wr1 + k4);
            float wav[4] = {wa.x, wa.y, wa.z, wa.w};
            float wbv[4] = {wb.x, wb.y, wb.z, wb.w};
            #pragma unroll
            for (int kk = 0; kk < 4; kk++) {
                const float* row = sx + (k4 * 4 + kk) * 256;
                float2 wa2 = make_float2(wav[kk], wav[kk]);
                float2 wb2 = make_float2(wbv[kk], wbv[kk]);
                #pragma unroll
                for (int p = 0; p < 4; p++) {
                    float4 vv = *(const float4*)(row + 4 * (j + 16 * p));
                    float2 vlo = make_float2(vv.x, vv.y);
                    float2 vhi = make_float2(vv.z, vv.w);
                    accA[p][0] = ffma2(wa2, vlo, accA[p][0]);
                    accA[p][1] = ffma2(wa2, vhi, accA[p][1]);
                    accB[p][0] = ffma2(wb2, vlo, accB[p][0]);
                    accB[p][1] = ffma2(wb2, vhi, accB[p][1]);
                }
            }
        }

        // Patch spectral filter: x' = (1/4) * H * diag(f) * H * x, then store
        #pragma unroll
        for (int ch = 0; ch < 2; ch++) {
            if (ch == 1 && !v1) break;
            int c = ch ? c1 : c0;
            float2 (*acc)[2] = ch ? accB : accA;
            float f0 = sF[c * 4 + 0], f1 = sF[c * 4 + 1];
            float f2 = sF[c * 4 + 2], f3 = sF[c * 4 + 3];
            float* hb = g_h + (((size_t)b * HID + c) * HW + 2 * py) * HW + c0b;
            #pragma unroll
            for (int p = 0; p < 4; p++) {
                float a  = acc[p][0].x, bb = acc[p][0].y;
                float cc = acc[p][1].x, dd = acc[p][1].y;
                float X0 = a + bb + cc + dd;
                float X1 = a - bb + cc - dd;
                float X2 = a + bb - cc - dd;
                float X3 = a - bb - cc + dd;
                X0 *= 0.25f * f0; X1 *= 0.25f * f1; X2 *= 0.25f * f2; X3 *= 0.25f * f3;
                float o0 = X0 + X1 + X2 + X3;
                float o1 = X0 - X1 + X2 - X3;
                float o2 = X0 + X1 - X2 - X3;
                float o3 = X0 - X1 - X2 + X3;
                int P = j + 16 * p;
                *(float2*)(hb + 2 * P)      = make_float2(o0, o1);
                *(float2*)(hb + HW + 2 * P) = make_float2(o2, o3);
            }
        }
    }
}

// ---------------------------------------------------------------------------
// Pass 2: depthwise 3x3 (170 groups x 2 outs) + exact GELU gate + 1x1 (170->64)
// grid (8, 32, 4): tile 32 wide x 8 tall. block 256 (warp = one pixel row).
// Double-buffered h tiles, hoisted staging addresses, f32x2 packed math.
// ---------------------------------------------------------------------------
extern "C" __global__ void __launch_bounds__(256)
pass2_kernel(const float* __restrict__ W_dw, const float* __restrict__ W_out,
             float* __restrict__ out)
{
    extern __shared__ float smem[];
    float*  sWo  = smem;                          // [170][64] W_out^T: sWo[c*64+o]
    float2* sDw1 = (float2*)(smem + HID * 64);    // [85][9] pairs (c=2g, 2g+1), x1 bank
    float2* sDw2 = sDw1 + 85 * 9;                 // [85][9] pairs, x2 bank (+170)
    float*  sh   = (float*)(sDw2 + 85 * 9);       // [2 buf][2 ch][10][36]

    const int tid = threadIdx.x;
    const int tx = tid & 31, ty = tid >> 5;
    const int b  = blockIdx.z;
    const int x0 = blockIdx.x * 32, y0 = blockIdx.y * 8;

    for (int idx = tid; idx < HID * 64; idx += 256) {
        int c = idx >> 6, o = idx & 63;
        sWo[idx] = W_out[o * HID + c];
    }
    for (int idx = tid; idx < 85 * 9; idx += 256) {
        int g = idx / 9, t = idx - 9 * g;
        sDw1[idx] = make_float2(W_dw[(2 * g) * 9 + t],       W_dw[(2 * g + 1) * 9 + t]);
        sDw2[idx] = make_float2(W_dw[(170 + 2 * g) * 9 + t], W_dw[(171 + 2 * g) * 9 + t]);
    }

    // Precompute staging descriptors (3 slots/thread covering 680 elements)
    const float* gp[3];
    int  soff[3];
    bool sval[3];
    #pragma unroll
    for (int s = 0; s < 3; s++) {
        int idx = tid + 256 * s;
        bool act = idx < 680;
        int ii = act ? idx : 0;
        int ch  = ii >= 340;
        int rem = ii - ch * 340;
        int row = rem / 34, col = rem - row * 34;
        int gy = y0 - 1 + row, gx = x0 - 1 + col;
        bool inb = (gy >= 0) && (gy < HW) && (gx >= 0) && (gx < HW);
        sval[s] = act && inb;
        soff[s] = ch * 360 + row * 36 + col;
        int gyc = inb ? gy : 0, gxc = inb ? gx : 0;
        gp[s] = g_h + (((size_t)b * HID + ch * 85) * HW + gyc) * HW + gxc;
        if (!act) soff[s] = 720 * 2 - 1; // harmless duplicate slot (written 0)
    }

    float2 acc[32];
    #pragma unroll
    for (int o = 0; o < 32; o++) acc[o] = make_float2(0.f, 0.f);

    // prefetch g = 0
    float pf[3];
    #pragma unroll
    for (int s = 0; s < 3; s++) pf[s] = sval[s] ? __ldg(gp[s]) : 0.f;

    int buf = 0;
    for (int g = 0; g < 85; g++) {
        float* shb = sh + buf * 720;
        shb[soff[0]] = pf[0];
        shb[soff[1]] = pf[1];
        if (tid < 680 - 512) shb[soff[2]] = pf[2];
        else if (soff[2] == 720 * 2 - 1) sh[soff[2]] = 0.f; // no-op slot
        __syncthreads();

        if (g < 84) {
            #pragma unroll
            for (int s = 0; s < 3; s++) {
                gp[s] += HWHW;
                pf[s] = sval[s] ? __ldg(gp[s]) : 0.f;
            }
        }

        // depthwise 3x3, packed over sub-channel pair (2g, 2g+1)
        const float*  b0 = shb + ty * 36 + tx;
        const float*  b1 = b0 + 360;
        const float2* w1 = sDw1 + g * 9;
        const float2* w2 = sDw2 + g * 9;
        float2 x1p = make_float2(0.f, 0.f);
        float2 x2p = make_float2(0.f, 0.f);
        #pragma unroll
        for (int ky = 0; ky < 3; ky++) {
            #pragma unroll
            for (int kx = 0; kx < 3; kx++) {
                float h0 = b0[ky * 36 + kx];
                float h1 = b1[ky * 36 + kx];
                x1p = ffma2(w1[ky * 3 + kx], make_float2(h0, h0), x1p);
                x2p = ffma2(w2[ky * 3 + kx], make_float2(h1, h1), x2p);
            }
        }
        float g0 = x1p.x * normcdff(x1p.x) * x2p.x;   // exact GELU(x1)*x2, c = 2g
        float g1 = x1p.y * normcdff(x1p.y) * x2p.y;   // c = 2g+1
        float2 g0p = make_float2(g0, g0);
        float2 g1p = make_float2(g1, g1);

        const float4* woA = (const float4*)(sWo + (2 * g) * 64);
        const float4* woB = woA + 16;
        #pragma unroll
        for (int o4 = 0; o4 < 16; o4++) {
            float4 wa = woA[o4];
            float4 wb = woB[o4];
            acc[2 * o4]     = ffma2(make_float2(wa.x, wa.y), g0p, acc[2 * o4]);
            acc[2 * o4]     = ffma2(make_float2(wb.x, wb.y), g1p, acc[2 * o4]);
            acc[2 * o4 + 1] = ffma2(make_float2(wa.z, wa.w), g0p, acc[2 * o4 + 1]);
            acc[2 * o4 + 1] = ffma2(make_float2(wb.z, wb.w), g1p, acc[2 * o4 + 1]);
        }
        buf ^= 1;
    }

    float* ob = out + (((size_t)b * 64) * HW + y0 + ty) * HW + x0 + tx;
    #pragma unroll
    for (int o = 0; o < 32; o++) {
        ob[(size_t)(2 * o) * HWHW]     = acc[o].x;
        ob[(size_t)(2 * o + 1) * HWHW] = acc[o].y;
    }
}

// ---------------------------------------------------------------------------
extern "C" void kernel_launch(void* const* d_in, const int* in_sizes, int n_in,
                              void* d_out, int out_size)
{
    const float* x     = (const float*)d_in[0];
    const float* W_in  = (const float*)d_in[1];
    const float* fftf  = (const float*)d_in[2];
    const float* W_dw  = (const float*)d_in[3];
    const float* W_out = (const float*)d_in[4];
    float* out = (float*)d_out;

    const int smem1 = (64 * 256 + HID * 4) * (int)sizeof(float);                  // ~68 KB
    const int smem2 = (HID * 64 + 4 * 85 * 9 + 2 * 720) * (int)sizeof(float);     // ~61 KB
    cudaFuncSetAttribute(pass1_kernel, cudaFuncAttributeMaxDynamicSharedMemorySize, smem1);
    cudaFuncSetAttribute(pass2_kernel, cudaFuncAttributeMaxDynamicSharedMemorySize, smem2);

    pass1_kernel<<<dim3(2, 128, 4), 256, smem1>>>(x, W_in, fftf);
    pass2_kernel<<<dim3(8, 32, 4), 256, smem2>>>(W_dw, W_out, out);
}

// round 4
// speedup vs baseline: 6.4650x; 1.2795x over previous
#include <cuda_runtime.h>
#include <cuda_bf16.h>

#define DIMC 64
#define HID  170
#define HW   256
#define HWHW (HW * HW)

// h scratch: [4][170][256][256] f32 = 178 MB (static __device__ => allocation-free)
__device__ float g_h[(size_t)4 * HID * HW * HW];

// Packed dual-FMA (Blackwell f32x2 pipe): d = a*b + c on 2 floats per instr.
__device__ __forceinline__ float2 ffma2(float2 a, float2 b, float2 c) {
    float2 d;
    asm("fma.rn.f32x2 %0, %1, %2, %3;"
        : "=l"(reinterpret_cast<unsigned long long&>(d))
        : "l"(reinterpret_cast<const unsigned long long&>(a)),
          "l"(reinterpret_cast<const unsigned long long&>(b)),
          "l"(reinterpret_cast<const unsigned long long&>(c)));
    return d;
}

// ---------------------------------------------------------------------------
// Pass 1: 1x1 conv (64 -> 170) + 2x2 patch spectral filter (4x4 Hadamard map)
// grid (2, 128, 4). block 256. Tile: 2 pixel rows x 128 cols => 64 patches.
// Each thread: 4 channels x 4 patches per chunk (x LDS reuse 4x).
// ---------------------------------------------------------------------------
extern "C" __global__ void __launch_bounds__(256, 2)
pass1_kernel(const float* __restrict__ x, const float* __restrict__ W_in,
             const float* __restrict__ fftf)
{
    extern __shared__ float smem[];
    float* sx = smem;               // [64][256] patch-grouped: sx[k*256 + 4*P + s]
    float* sF = sx + 64 * 256;      // [170][4]

    const int tid = threadIdx.x;
    const int b   = blockIdx.z;
    const int py  = blockIdx.y;          // patch row (pixel rows 2*py, 2*py+1)
    const int c0b = blockIdx.x * 128;    // pixel col base

    for (int i = tid; i < HID * 4; i += 256) sF[i] = fftf[i];

    // Stage x tile: 64 ch x 2 rows x 128 cols as float4 (coalesced), patch-grouped
    const float* xb = x + (size_t)b * 64 * HWHW;
    for (int idx = tid; idx < 4096; idx += 256) {
        int k  = idx >> 6;
        int r  = (idx >> 5) & 1;
        int c4 = idx & 31;
        float4 v = *(const float4*)(xb + ((size_t)k * HW + 2 * py + r) * HW + c0b + 4 * c4);
        int base = k * 256 + 8 * c4 + 2 * r;
        *(float2*)(sx + base)     = make_float2(v.x, v.y);
        *(float2*)(sx + base + 4) = make_float2(v.z, v.w);
    }
    __syncthreads();

    const int i = tid >> 4;   // channel slot 0..15
    const int j = tid & 15;   // patch slot: patches j, j+16, j+32, j+48

    #pragma unroll
    for (int cb = 0; cb < 192; cb += 64) {
        int cch[4];
        bool val[4];
        const float4* wr[4];
        #pragma unroll
        for (int cc = 0; cc < 4; cc++) {
            int c = cb + 16 * cc + i;
            val[cc] = (c < HID);
            cch[cc] = c;
            wr[cc]  = (const float4*)(W_in + (val[cc] ? c : 0) * 64);
        }
        if (!val[0]) continue;

        float2 acc[4][4][2];   // [ch][patch][lo/hi]
        #pragma unroll
        for (int cc = 0; cc < 4; cc++)
            #pragma unroll
            for (int p = 0; p < 4; p++)
                acc[cc][p][0] = acc[cc][p][1] = make_float2(0.f, 0.f);

        #pragma unroll
        for (int k4 = 0; k4 < 16; k4++) {
            float4 w[4];
            #pragma unroll
            for (int cc = 0; cc < 4; cc++) w[cc] = __ldg(wr[cc] + k4);
            #pragma unroll
            for (int kk = 0; kk < 4; kk++) {
                const float* row = sx + (k4 * 4 + kk) * 256;
                float ws[4];
                ws[0] = (kk == 0) ? w[0].x : (kk == 1) ? w[0].y : (kk == 2) ? w[0].z : w[0].w;
                ws[1] = (kk == 0) ? w[1].x : (kk == 1) ? w[1].y : (kk == 2) ? w[1].z : w[1].w;
                ws[2] = (kk == 0) ? w[2].x : (kk == 1) ? w[2].y : (kk == 2) ? w[2].z : w[2].w;
                ws[3] = (kk == 0) ? w[3].x : (kk == 1) ? w[3].y : (kk == 2) ? w[3].z : w[3].w;
                #pragma unroll
                for (int p = 0; p < 4; p++) {
                    float4 vv = *(const float4*)(row + 4 * (j + 16 * p));
                    float2 vlo = make_float2(vv.x, vv.y);
                    float2 vhi = make_float2(vv.z, vv.w);
                    #pragma unroll
                    for (int cc = 0; cc < 4; cc++) {
                        float2 w2 = make_float2(ws[cc], ws[cc]);
                        acc[cc][p][0] = ffma2(w2, vlo, acc[cc][p][0]);
                        acc[cc][p][1] = ffma2(w2, vhi, acc[cc][p][1]);
                    }
                }
            }
        }

        // Patch spectral filter: x' = (1/4) * H * diag(f) * H * x, then store
        #pragma unroll
        for (int cc = 0; cc < 4; cc++) {
            if (!val[cc]) continue;
            int c = cch[cc];
            float f0 = sF[c * 4 + 0], f1 = sF[c * 4 + 1];
            float f2 = sF[c * 4 + 2], f3 = sF[c * 4 + 3];
            float* hb = g_h + (((size_t)b * HID + c) * HW + 2 * py) * HW + c0b;
            #pragma unroll
            for (int p = 0; p < 4; p++) {
                float a  = acc[cc][p][0].x, bb = acc[cc][p][0].y;
                float cv = acc[cc][p][1].x, dd = acc[cc][p][1].y;
                float X0 = a + bb + cv + dd;
                float X1 = a - bb + cv - dd;
                float X2 = a + bb - cv - dd;
                float X3 = a - bb - cv + dd;
                X0 *= 0.25f * f0; X1 *= 0.25f * f1; X2 *= 0.25f * f2; X3 *= 0.25f * f3;
                float o0 = X0 + X1 + X2 + X3;
                float o1 = X0 - X1 + X2 - X3;
                float o2 = X0 + X1 - X2 - X3;
                float o3 = X0 - X1 - X2 + X3;
                int P = j + 16 * p;
                *(float2*)(hb + 2 * P)      = make_float2(o0, o1);
                *(float2*)(hb + HW + 2 * P) = make_float2(o2, o3);
            }
        }
    }
}

// ---------------------------------------------------------------------------
// Pass 2: depthwise 3x3 + exact GELU gate + 1x1 (170->64), chunked two-phase:
// per chunk of 5 groups (10 channels): phase A = dwconv+gelu -> sG[10][256],
// phase B = register-blocked GEMM (8 outs x 8 px per thread).
// grid (8, 32, 4): pixel tile 32 wide x 8 tall. block 256.
// ---------------------------------------------------------------------------
extern "C" __global__ void __launch_bounds__(256, 2)
pass2_kernel(const float* __restrict__ W_dw, const float* __restrict__ W_out,
             float* __restrict__ out)
{
    extern __shared__ float smem[];
    float*  sWo  = smem;                          // [170][64] W_out^T: sWo[c*64+o]
    float2* sDw1 = (float2*)(smem + HID * 64);    // [85][9] pairs (c=2g,2g+1), x1 bank
    float2* sDw2 = sDw1 + 85 * 9;                 // [85][9] pairs, x2 bank (+170)
    float*  sh   = (float*)(sDw2 + 85 * 9);       // [5 groups][2 ch][10][36] = [5][720]
    float*  sG   = sh + 5 * 720;                  // [10][256] gated chunk

    const int tid = threadIdx.x;
    const int tx = tid & 31, ty = tid >> 5;
    const int b  = blockIdx.z;
    const int x0 = blockIdx.x * 32, y0 = blockIdx.y * 8;
    const int mi = ty;        // out block: outs mi*8 .. mi*8+7
    const int nj = tx;        // px  block: px  nj*8 .. nj*8+7

    for (int idx = tid; idx < HID * 64; idx += 256) {
        int c = idx >> 6, o = idx & 63;
        sWo[idx] = W_out[o * HID + c];
    }
    for (int idx = tid; idx < 85 * 9; idx += 256) {
        int g = idx / 9, t = idx - 9 * g;
        sDw1[idx] = make_float2(W_dw[(2 * g) * 9 + t],       W_dw[(2 * g + 1) * 9 + t]);
        sDw2[idx] = make_float2(W_dw[(170 + 2 * g) * 9 + t], W_dw[(171 + 2 * g) * 9 + t]);
    }

    // Staging descriptors: 3 slots/thread covering 680 elements of one group-pair
    const float* gp[3];
    int  soff[3];
    bool sval[3];
    #pragma unroll
    for (int s = 0; s < 3; s++) {
        int idx = tid + 256 * s;
        bool act = idx < 680;
        int ii = act ? idx : 0;
        int ch  = ii >= 340;
        int rem = ii - ch * 340;
        int row = rem / 34, col = rem - row * 34;
        int gy = y0 - 1 + row, gx = x0 - 1 + col;
        bool inb = (gy >= 0) && (gy < HW) && (gx >= 0) && (gx < HW);
        sval[s] = act && inb;
        soff[s] = ch * 360 + row * 36 + col;
        gp[s] = g_h + (((size_t)b * HID + ch * 85) * HW + (inb ? gy : 0)) * HW + (inb ? gx : 0);
    }

    float2 acc[8][4];   // [out][px-pair]
    #pragma unroll
    for (int o = 0; o < 8; o++)
        #pragma unroll
        for (int pp = 0; pp < 4; pp++) acc[o][pp] = make_float2(0.f, 0.f);

    __syncthreads();

    for (int ck = 0; ck < 17; ck++) {
        // ---- stage h for 5 groups (batched LDGs for MLP, then STS) ----
        float pf[15];
        #pragma unroll
        for (int gi = 0; gi < 5; gi++) {
            size_t goff = (size_t)(ck * 5 + gi) * HWHW;
            #pragma unroll
            for (int s = 0; s < 3; s++)
                pf[gi * 3 + s] = sval[s] ? __ldg(gp[s] + goff) : 0.f;
        }
        #pragma unroll
        for (int gi = 0; gi < 5; gi++) {
            float* dst = sh + gi * 720;
            dst[soff[0]] = pf[gi * 3 + 0];
            dst[soff[1]] = pf[gi * 3 + 1];
            if (tid < 680 - 512) dst[soff[2]] = pf[gi * 3 + 2];
        }
        __syncthreads();

        // ---- phase A: dwconv + exact GELU gate -> sG ----
        #pragma unroll
        for (int gi = 0; gi < 5; gi++) {
            int g = ck * 5 + gi;
            const float*  b0 = sh + gi * 720 + ty * 36 + tx;
            const float*  b1 = b0 + 360;
            const float2* w1 = sDw1 + g * 9;
            const float2* w2 = sDw2 + g * 9;
            float2 x1p = make_float2(0.f, 0.f);
            float2 x2p = make_float2(0.f, 0.f);
            #pragma unroll
            for (int ky = 0; ky < 3; ky++) {
                #pragma unroll
                for (int kx = 0; kx < 3; kx++) {
                    float h0 = b0[ky * 36 + kx];
                    float h1 = b1[ky * 36 + kx];
                    x1p = ffma2(w1[ky * 3 + kx], make_float2(h0, h0), x1p);
                    x2p = ffma2(w2[ky * 3 + kx], make_float2(h1, h1), x2p);
                }
            }
            sG[(2 * gi) * 256 + tid]     = x1p.x * normcdff(x1p.x) * x2p.x;
            sG[(2 * gi + 1) * 256 + tid] = x1p.y * normcdff(x1p.y) * x2p.y;
        }
        __syncthreads();

        // ---- phase B: GEMM accumulate (8 outs x 8 px per thread) ----
        #pragma unroll
        for (int kc = 0; kc < 10; kc++) {
            int c = ck * 10 + kc;
            const float4* wv = (const float4*)(sWo + c * 64 + mi * 8);
            float4 wA = wv[0], wB = wv[1];
            const float4* gv = (const float4*)(sG + kc * 256 + nj * 8);
            float4 gA = gv[0], gB = gv[1];
            float2 g0 = make_float2(gA.x, gA.y);
            float2 g1 = make_float2(gA.z, gA.w);
            float2 g2 = make_float2(gB.x, gB.y);
            float2 g3 = make_float2(gB.z, gB.w);
            float ws[8] = {wA.x, wA.y, wA.z, wA.w, wB.x, wB.y, wB.z, wB.w};
            #pragma unroll
            for (int o = 0; o < 8; o++) {
                float2 w2 = make_float2(ws[o], ws[o]);
                acc[o][0] = ffma2(w2, g0, acc[o][0]);
                acc[o][1] = ffma2(w2, g1, acc[o][1]);
                acc[o][2] = ffma2(w2, g2, acc[o][2]);
                acc[o][3] = ffma2(w2, g3, acc[o][3]);
            }
        }
        __syncthreads();
    }

    // ---- store: thread's 8 px = one row segment of 8 cols ----
    const int orow = nj >> 2;
    const int ocol = (nj & 3) * 8;
    float* ob = out + (((size_t)b * 64 + mi * 8) * HW + y0 + orow) * HW + x0 + ocol;
    #pragma unroll
    for (int o = 0; o < 8; o++) {
        float4 v0 = make_float4(acc[o][0].x, acc[o][0].y, acc[o][1].x, acc[o][1].y);
        float4 v1 = make_float4(acc[o][2].x, acc[o][2].y, acc[o][3].x, acc[o][3].y);
        *(float4*)(ob + (size_t)o * HWHW)     = v0;
        *(float4*)(ob + (size_t)o * HWHW + 4) = v1;
    }
}

// ---------------------------------------------------------------------------
extern "C" void kernel_launch(void* const* d_in, const int* in_sizes, int n_in,
                              void* d_out, int out_size)
{
    const float* x     = (const float*)d_in[0];
    const float* W_in  = (const float*)d_in[1];
    const float* fftf  = (const float*)d_in[2];
    const float* W_dw  = (const float*)d_in[3];
    const float* W_out = (const float*)d_in[4];
    float* out = (float*)d_out;

    const int smem1 = (64 * 256 + HID * 4) * (int)sizeof(float);                       // ~68 KB
    const int smem2 = (HID * 64 + 4 * 85 * 9 + 5 * 720 + 10 * 256) * (int)sizeof(float); // ~80 KB
    cudaFuncSetAttribute(pass1_kernel, cudaFuncAttributeMaxDynamicSharedMemorySize, smem1);
    cudaFuncSetAttribute(pass2_kernel, cudaFuncAttributeMaxDynamicSharedMemorySize, smem2);

    pass1_kernel<<<dim3(2, 128, 4), 256, smem1>>>(x, W_in, fftf);
    pass2_kernel<<<dim3(8, 32, 4), 256, smem2>>>(W_dw, W_out, out);
}